// round 3
// baseline (speedup 1.0000x reference)
#include <cuda_runtime.h>
#include <cuda_bf16.h>

// Problem shape (fixed by the dataset): N=50000 nodes, D=64, E=800000 edges, HID=64.
// Strategy:
//   Pa[n][j] = emb[n] . W1[0:64 , j] + b1[j]
//   Pb[n][j] = emb[n] . W1[64:128, j]
//   out[e]   = W2 . relu(Pa[src[e]] + Pb[dst[e]]) + b2
// Precompute factors the big GEMM through nodes (64x fewer FLOPs); edge kernel is
// then L2-gather bound (both 12.8MB tables fit in the 126MB L2).
// NOTE: edge_index is int32 on device (JAX x64 disabled downcasts the reference's
// "int64" randint to int32). Reading it as int64 was the cause of the round-1/2
// trap 717 (wild generic addresses hitting the shared aperture).

#define MAX_NODES 50048
#define D 64
#define HID 64

__device__ float g_Pa[MAX_NODES * HID];   // includes b1
__device__ float g_Pb[MAX_NODES * HID];

// ---------------------------------------------------------------------------
// Kernel 1: P = emb @ [W1a | W1b]   (50000x64 @ 64x128), smem-tiled GEMM.
// Block: 256 threads, 64 nodes x 128 outputs tile. Each thread: 8 nodes x 4 outs.
// Static shared only (48KB): Ws[64][128] (k-major W) + As[64][64] node-major.
// ---------------------------------------------------------------------------
__global__ void precompute_kernel(const float* __restrict__ emb,
                                  const float* __restrict__ W1,
                                  const float* __restrict__ b1,
                                  int n_nodes)
{
    __shared__ float Ws[64 * 128];   // Ws[k*128 + o]; o<64 -> W1a[:,o], o>=64 -> W1b[:,o-64]
    __shared__ float As[64 * 64];    // As[n*64 + k] node-major

    const int tid = threadIdx.x;     // 256 threads
    const int node0 = blockIdx.x * 64;

    // Load W reordered so k is the row: Ws[k][o] = W1[k + 64*(o>=64)][o&63]
    for (int i = tid; i < 64 * 128; i += 256) {
        int k = i >> 7, o = i & 127;
        int half = o >> 6, j = o & 63;
        Ws[i] = W1[(k + 64 * half) * HID + j];
    }
    // Load emb tile node-major (fully coalesced, float4).
    {
        const int nloc = tid >> 2;          // 0..63
        const int kq   = (tid & 3) << 4;    // 0,16,32,48
        int gn = node0 + nloc;
        float4 v0 = make_float4(0.f, 0.f, 0.f, 0.f), v1 = v0, v2 = v0, v3 = v0;
        if (gn < n_nodes) {
            const float4* src = (const float4*)(emb + (size_t)gn * D + kq);
            v0 = src[0]; v1 = src[1]; v2 = src[2]; v3 = src[3];
        }
        float4* dst = (float4*)(As + nloc * 64 + kq);
        dst[0] = v0; dst[1] = v1; dst[2] = v2; dst[3] = v3;
    }
    __syncthreads();

    const int tx = tid & 31;        // output group: o = tx*4
    const int ty = tid >> 5;        // node group:  n = ty*8 ..
    float acc[8][4];
    #pragma unroll
    for (int i = 0; i < 8; i++)
        #pragma unroll
        for (int j = 0; j < 4; j++) acc[i][j] = 0.f;

    #pragma unroll 4
    for (int k = 0; k < 64; k++) {
        float4 bv = *(const float4*)(Ws + k * 128 + (tx << 2));
        #pragma unroll
        for (int i = 0; i < 8; i++) {
            float a = As[((ty << 3) + i) * 64 + k];   // uniform per warp -> broadcast
            acc[i][0] = fmaf(a, bv.x, acc[i][0]);
            acc[i][1] = fmaf(a, bv.y, acc[i][1]);
            acc[i][2] = fmaf(a, bv.z, acc[i][2]);
            acc[i][3] = fmaf(a, bv.w, acc[i][3]);
        }
    }

    const int o = tx << 2;
    const bool isA = (o < 64);
    const int j = o & 63;
    float4 bias = make_float4(0.f, 0.f, 0.f, 0.f);
    if (isA) bias = *(const float4*)(b1 + j);

    float* base = (isA ? g_Pa : g_Pb) + j;
    #pragma unroll
    for (int i = 0; i < 8; i++) {
        int n = node0 + (ty << 3) + i;
        if (n < n_nodes) {
            float4 r;
            r.x = acc[i][0] + bias.x;
            r.y = acc[i][1] + bias.y;
            r.z = acc[i][2] + bias.z;
            r.w = acc[i][3] + bias.w;
            *(float4*)(base + (size_t)n * HID) = r;
        }
    }
}

// ---------------------------------------------------------------------------
// Kernel 2: per-edge gather + relu + dot(W2). 16 lanes per edge (2 edges/warp).
// Each 16-lane group reads a contiguous 256B row from Pa and Pb (coalesced).
// ---------------------------------------------------------------------------
__global__ void edge_kernel(const int* __restrict__ ei,
                            const float* __restrict__ W2,
                            const float* __restrict__ b2,
                            float* __restrict__ out,
                            int E)
{
    int gtid = blockIdx.x * blockDim.x + threadIdx.x;
    int warp = gtid >> 5;
    int lane = threadIdx.x & 31;
    int t = lane & 15;               // position within edge group
    int g = lane >> 4;               // which edge of the pair

    float4 w2v = *(const float4*)(W2 + (t << 2));
    float b2v = __ldg(b2);

    int e = warp * 2 + g;
    int ec = (e < E) ? e : (E - 1);

    int s = 0, d = 0;
    if (t == 0) {
        s = __ldg(ei + ec);
        d = __ldg(ei + E + ec);
    }
    s = __shfl_sync(0xffffffffu, s, lane & 16);
    d = __shfl_sync(0xffffffffu, d, lane & 16);

    const float4* pa = (const float4*)(g_Pa + (size_t)s * HID);
    const float4* pb = (const float4*)(g_Pb + (size_t)d * HID);
    float4 a = pa[t];
    float4 b = pb[t];

    float p = fmaxf(a.x + b.x, 0.f) * w2v.x
            + fmaxf(a.y + b.y, 0.f) * w2v.y
            + fmaxf(a.z + b.z, 0.f) * w2v.z
            + fmaxf(a.w + b.w, 0.f) * w2v.w;

    // reduce across the 16 lanes of this edge group
    p += __shfl_xor_sync(0xffffffffu, p, 8);
    p += __shfl_xor_sync(0xffffffffu, p, 4);
    p += __shfl_xor_sync(0xffffffffu, p, 2);
    p += __shfl_xor_sync(0xffffffffu, p, 1);

    if (t == 0 && e < E) out[e] = p + b2v;
}

// ---------------------------------------------------------------------------
extern "C" void kernel_launch(void* const* d_in, const int* in_sizes, int n_in,
                              void* d_out, int out_size)
{
    const float* emb = (const float*)d_in[0];
    const int*   ei  = (const int*)d_in[1];     // int32! (JAX x64 disabled)
    const float* W1  = (const float*)d_in[2];
    const float* b1  = (const float*)d_in[3];
    const float* W2  = (const float*)d_in[4];
    const float* b2  = (const float*)d_in[5];
    float*       out = (float*)d_out;

    int n_nodes = in_sizes[0] / D;        // 50000
    int E       = in_sizes[1] / 2;        // 800000

    int pre_blocks = (n_nodes + 63) / 64;
    precompute_kernel<<<pre_blocks, 256>>>(emb, W1, b1, n_nodes);

    long long warps = ((long long)E + 1) / 2;
    long long threads = warps * 32;
    int blocks = (int)((threads + 255) / 256);
    edge_kernel<<<blocks, 256>>>(ei, W2, b2, out, E);
}

// round 4
// speedup vs baseline: 1.2153x; 1.2153x over previous
#include <cuda_runtime.h>
#include <cuda_fp16.h>

// N=50000 nodes, D=64, E=800000 edges, HID=64.
//   Pa[n][j] = emb[n] . W1[0:64 , j] + b1[j]   (stored fp16)
//   Pb[n][j] = emb[n] . W1[64:128, j]          (stored fp16)
//   out[e]   = W2 . relu(Pa[src[e]] + Pb[dst[e]]) + b2   (fp32 math)
// fp16 tables: a node row is 128B = 1 cache line -> half the L1 wavefronts and
// half the L2 traffic of the fp32 version (R3: edge kernel was L1tex-bound 55%).

#define MAX_NODES 50048
#define D 64
#define HID 64

__device__ __half g_Pa[MAX_NODES * HID];   // includes b1
__device__ __half g_Pb[MAX_NODES * HID];

// ---------------------------------------------------------------------------
// Kernel 1: P = emb @ [W1a | W1b]  (50000x64 @ 64x128), smem-tiled, fp16 out.
// Block: 256 threads, tile 64 nodes x 128 outputs; thread: 8 nodes x 4 outs.
// ---------------------------------------------------------------------------
__global__ void precompute_kernel(const float* __restrict__ emb,
                                  const float* __restrict__ W1,
                                  const float* __restrict__ b1,
                                  int n_nodes)
{
    __shared__ float Ws[64 * 128];   // Ws[k*128 + o]; o<64 -> W1a[:,o], o>=64 -> W1b[:,o-64]
    __shared__ float As[64 * 64];    // As[n*64 + k] node-major

    const int tid = threadIdx.x;
    const int node0 = blockIdx.x * 64;

    for (int i = tid; i < 64 * 128; i += 256) {
        int k = i >> 7, o = i & 127;
        int half_ = o >> 6, j = o & 63;
        Ws[i] = W1[(k + 64 * half_) * HID + j];
    }
    {
        const int nloc = tid >> 2;
        const int kq   = (tid & 3) << 4;
        int gn = node0 + nloc;
        float4 v0 = make_float4(0.f,0.f,0.f,0.f), v1 = v0, v2 = v0, v3 = v0;
        if (gn < n_nodes) {
            const float4* src = (const float4*)(emb + (size_t)gn * D + kq);
            v0 = src[0]; v1 = src[1]; v2 = src[2]; v3 = src[3];
        }
        float4* dst = (float4*)(As + nloc * 64 + kq);
        dst[0] = v0; dst[1] = v1; dst[2] = v2; dst[3] = v3;
    }
    __syncthreads();

    const int tx = tid & 31;        // o = tx*4
    const int ty = tid >> 5;        // n = ty*8 ..
    float acc[8][4];
    #pragma unroll
    for (int i = 0; i < 8; i++)
        #pragma unroll
        for (int j = 0; j < 4; j++) acc[i][j] = 0.f;

    #pragma unroll 4
    for (int k = 0; k < 64; k++) {
        float4 bv = *(const float4*)(Ws + k * 128 + (tx << 2));
        #pragma unroll
        for (int i = 0; i < 8; i++) {
            float a = As[((ty << 3) + i) * 64 + k];   // warp-uniform broadcast
            acc[i][0] = fmaf(a, bv.x, acc[i][0]);
            acc[i][1] = fmaf(a, bv.y, acc[i][1]);
            acc[i][2] = fmaf(a, bv.z, acc[i][2]);
            acc[i][3] = fmaf(a, bv.w, acc[i][3]);
        }
    }

    const int o = tx << 2;
    const bool isA = (o < 64);
    const int j = o & 63;
    float4 bias = make_float4(0.f,0.f,0.f,0.f);
    if (isA) bias = *(const float4*)(b1 + j);

    __half* base = (isA ? g_Pa : g_Pb) + j;
    #pragma unroll
    for (int i = 0; i < 8; i++) {
        int n = node0 + (ty << 3) + i;
        if (n < n_nodes) {
            __half2 h01 = __floats2half2_rn(acc[i][0] + bias.x, acc[i][1] + bias.y);
            __half2 h23 = __floats2half2_rn(acc[i][2] + bias.z, acc[i][3] + bias.w);
            uint2 pk;
            pk.x = *(unsigned int*)&h01;
            pk.y = *(unsigned int*)&h23;
            *(uint2*)(base + (size_t)n * HID) = pk;   // 8B aligned (j % 4 == 0)
        }
    }
}

// ---------------------------------------------------------------------------
// Kernel 2: gather + relu + dot(W2). 8 lanes/edge (4 edges/warp).
// Each 8-lane group reads one 128B line from Pa and one from Pb.
// ---------------------------------------------------------------------------
__global__ void edge_kernel(const int* __restrict__ ei,
                            const float* __restrict__ W2,
                            const float* __restrict__ b2,
                            float* __restrict__ out,
                            int E)
{
    int gtid = blockIdx.x * blockDim.x + threadIdx.x;
    int warp = gtid >> 5;
    int lane = threadIdx.x & 31;
    int t = lane & 7;                // position within edge group (8 halves each)
    int g = lane >> 3;               // which of 4 edges in this warp

    float4 w0 = *(const float4*)(W2 + (t << 3));
    float4 w1 = *(const float4*)(W2 + (t << 3) + 4);
    float b2v = __ldg(b2);

    int e = warp * 4 + g;
    int ec = (e < E) ? e : (E - 1);

    int s = 0, d = 0;
    if (t == 0) {
        s = __ldg(ei + ec);
        d = __ldg(ei + E + ec);
    }
    s = __shfl_sync(0xffffffffu, s, lane & 24);
    d = __shfl_sync(0xffffffffu, d, lane & 24);

    const uint4* pa = (const uint4*)(g_Pa + (size_t)s * HID);  // row = 128B
    const uint4* pb = (const uint4*)(g_Pb + (size_t)d * HID);
    uint4 av = pa[t];
    uint4 bv = pb[t];

    float p;
    {
        float2 a0 = __half22float2(*(__half2*)&av.x);
        float2 b0 = __half22float2(*(__half2*)&bv.x);
        float2 a1 = __half22float2(*(__half2*)&av.y);
        float2 b1_ = __half22float2(*(__half2*)&bv.y);
        float2 a2 = __half22float2(*(__half2*)&av.z);
        float2 b2_ = __half22float2(*(__half2*)&bv.z);
        float2 a3 = __half22float2(*(__half2*)&av.w);
        float2 b3 = __half22float2(*(__half2*)&bv.w);
        p = fmaxf(a0.x + b0.x, 0.f) * w0.x
          + fmaxf(a0.y + b0.y, 0.f) * w0.y
          + fmaxf(a1.x + b1_.x, 0.f) * w0.z
          + fmaxf(a1.y + b1_.y, 0.f) * w0.w
          + fmaxf(a2.x + b2_.x, 0.f) * w1.x
          + fmaxf(a2.y + b2_.y, 0.f) * w1.y
          + fmaxf(a3.x + b3.x, 0.f) * w1.z
          + fmaxf(a3.y + b3.y, 0.f) * w1.w;
    }

    // reduce across the 8 lanes of this edge group
    p += __shfl_xor_sync(0xffffffffu, p, 4);
    p += __shfl_xor_sync(0xffffffffu, p, 2);
    p += __shfl_xor_sync(0xffffffffu, p, 1);

    if (t == 0 && e < E) out[e] = p + b2v;
}

// ---------------------------------------------------------------------------
extern "C" void kernel_launch(void* const* d_in, const int* in_sizes, int n_in,
                              void* d_out, int out_size)
{
    const float* emb = (const float*)d_in[0];
    const int*   ei  = (const int*)d_in[1];     // int32 (JAX x64 disabled)
    const float* W1  = (const float*)d_in[2];
    const float* b1  = (const float*)d_in[3];
    const float* W2  = (const float*)d_in[4];
    const float* b2  = (const float*)d_in[5];
    float*       out = (float*)d_out;

    int n_nodes = in_sizes[0] / D;        // 50000
    int E       = in_sizes[1] / 2;        // 800000

    int pre_blocks = (n_nodes + 63) / 64;
    precompute_kernel<<<pre_blocks, 256>>>(emb, W1, b1, n_nodes);

    long long warps = ((long long)E + 3) / 4;
    long long threads = warps * 32;
    int blocks = (int)((threads + 255) / 256);
    edge_kernel<<<blocks, 256>>>(ei, W2, b2, out, E);
}

// round 5
// speedup vs baseline: 1.6794x; 1.3819x over previous
#include <cuda_runtime.h>
#include <cuda_fp16.h>

// N=50000 nodes, D=64, E=800000 edges, HID=64.
//   Pa[n][j] = emb[n] . W1[0:64 , j] + b1[j]   (stored fp16)
//   Pb[n][j] = emb[n] . W1[64:128, j]          (stored fp16)
//   out[e]   = W2 . relu(Pa[src[e]] + Pb[dst[e]]) + b2
// R5: precompute moved to tensor cores (mma.sync m16n8k16, fp16 in / fp32 acc),
//     edge epilogue moved to HADD2/HMAX2 to cut issue pressure.

#define MAX_NODES 50048
#define D 64
#define HID 64

__device__ __half g_Pa[MAX_NODES * HID];   // includes b1
__device__ __half g_Pb[MAX_NODES * HID];

// ---------------------------------------------------------------------------
// Kernel 1: P = emb @ [W1a | W1b]  (50000x64 @ 64x128) via HMMA.
// Block: 256 threads (8 warps), tile 128 rows x 128 outs. Warp: 16 rows, all 128
// outs = 16 n-tiles x 4 k-steps of m16n8k16. Smem stride 72 halves -> the mma
// fragment loads are exactly bank = lane (conflict-free).
// ---------------------------------------------------------------------------
__global__ void precompute_mma(const float* __restrict__ emb,
                               const float* __restrict__ W1,
                               const float* __restrict__ b1,
                               int n_nodes)
{
    __shared__ __half As[128 * 72];   // As[r][k], r = local node row
    __shared__ __half Bs[128 * 72];   // Bs[o][k], o = output col (0..63 Pa, 64..127 Pb)

    const int tid = threadIdx.x;
    const int node0 = blockIdx.x * 128;

    // Load emb tile (128 x 64 fp32), convert to fp16. Coalesced float4 reads.
    {
        int r  = tid >> 1;
        int c0 = (tid & 1) * 32;
        int gn = node0 + r;
        __half2* dst = (__half2*)&As[r * 72 + c0];
        if (gn < n_nodes) {
            const float4* src = (const float4*)(emb + (size_t)gn * D + c0);
            #pragma unroll
            for (int q = 0; q < 8; q++) {
                float4 v = src[q];
                dst[q * 2]     = __floats2half2_rn(v.x, v.y);
                dst[q * 2 + 1] = __floats2half2_rn(v.z, v.w);
            }
        } else {
            #pragma unroll
            for (int q = 0; q < 16; q++) dst[q] = __half2half2(__float2half(0.f));
        }
    }
    // Load W1 transposed into Bs[o][k] (coalesced over o's column reads):
    //   o<64:  Bs[o][k] = W1[k][o]        (W1a)
    //   o>=64: Bs[o][k] = W1[64+k][o-64]  (W1b)
    for (int i = tid; i < 128 * 64; i += 256) {
        int k = i >> 7, o = i & 127;
        float w = W1[((o < 64) ? k : 64 + k) * HID + (o & 63)];
        Bs[o * 72 + k] = __float2half(w);
    }
    __syncthreads();

    const int warp = tid >> 5, lane = tid & 31;
    const int g = lane >> 2, tig = lane & 3;
    const int mrow = warp * 16;

    float acc[16][4];
    #pragma unroll
    for (int nt = 0; nt < 16; nt++)
        #pragma unroll
        for (int q = 0; q < 4; q++) acc[nt][q] = 0.f;

    #pragma unroll
    for (int kt = 0; kt < 4; kt++) {
        const __half* abase = &As[(mrow + g) * 72 + kt * 16 + tig * 2];
        unsigned int a0 = *(const unsigned int*)(abase);
        unsigned int a1 = *(const unsigned int*)(abase + 8 * 72);
        unsigned int a2 = *(const unsigned int*)(abase + 8);
        unsigned int a3 = *(const unsigned int*)(abase + 8 * 72 + 8);
        #pragma unroll
        for (int nt = 0; nt < 16; nt++) {
            const __half* bbase = &Bs[(nt * 8 + g) * 72 + kt * 16 + tig * 2];
            unsigned int b0 = *(const unsigned int*)(bbase);
            unsigned int b1r = *(const unsigned int*)(bbase + 8);
            asm volatile(
                "mma.sync.aligned.m16n8k16.row.col.f32.f16.f16.f32 "
                "{%0,%1,%2,%3}, {%4,%5,%6,%7}, {%8,%9}, {%0,%1,%2,%3};"
                : "+f"(acc[nt][0]), "+f"(acc[nt][1]), "+f"(acc[nt][2]), "+f"(acc[nt][3])
                : "r"(a0), "r"(a1), "r"(a2), "r"(a3), "r"(b0), "r"(b1r));
        }
    }

    // Epilogue: bias (Pa half only) + fp16 pack + store.
    const int nc = tig * 2;
    const int n0 = node0 + mrow + g;
    const int n1 = n0 + 8;
    #pragma unroll
    for (int nt = 0; nt < 16; nt++) {
        int o = nt * 8 + nc;
        float bx = 0.f, by = 0.f;
        if (o < 64) { bx = b1[o]; by = b1[o + 1]; }
        __half* tab = (o < 64) ? g_Pa : g_Pb;
        int col = o & 63;
        if (n0 < n_nodes)
            *(__half2*)(tab + (size_t)n0 * HID + col) =
                __floats2half2_rn(acc[nt][0] + bx, acc[nt][1] + by);
        if (n1 < n_nodes)
            *(__half2*)(tab + (size_t)n1 * HID + col) =
                __floats2half2_rn(acc[nt][2] + bx, acc[nt][3] + by);
    }
}

// ---------------------------------------------------------------------------
// Kernel 2: gather + relu + dot(W2). 8 lanes/edge (4 edges/warp).
// Each 8-lane group reads one 128B line from Pa and one from Pb.
// Add+ReLU in packed fp16 (HADD2/HMAX2), dot in fp32.
// ---------------------------------------------------------------------------
__global__ void edge_kernel(const int* __restrict__ ei,
                            const float* __restrict__ W2,
                            const float* __restrict__ b2,
                            float* __restrict__ out,
                            int E)
{
    int gtid = blockIdx.x * blockDim.x + threadIdx.x;
    int warp = gtid >> 5;
    int lane = threadIdx.x & 31;
    int t = lane & 7;                // position within edge group (8 halves each)
    int g = lane >> 3;               // which of 4 edges in this warp

    float4 w0 = *(const float4*)(W2 + (t << 3));
    float4 w1 = *(const float4*)(W2 + (t << 3) + 4);
    float b2v = __ldg(b2);

    int e = warp * 4 + g;
    int ec = (e < E) ? e : (E - 1);

    int s = 0, d = 0;
    if (t == 0) {
        s = __ldg(ei + ec);
        d = __ldg(ei + E + ec);
    }
    s = __shfl_sync(0xffffffffu, s, lane & 24);
    d = __shfl_sync(0xffffffffu, d, lane & 24);

    const uint4* pa = (const uint4*)(g_Pa + (size_t)s * HID);  // row = 128B
    const uint4* pb = (const uint4*)(g_Pb + (size_t)d * HID);
    uint4 av = pa[t];
    uint4 bv = pb[t];

    const __half2 z2 = __half2half2(__float2half(0.f));
    __half2 s0 = __hmax2(__hadd2(*(__half2*)&av.x, *(__half2*)&bv.x), z2);
    __half2 s1 = __hmax2(__hadd2(*(__half2*)&av.y, *(__half2*)&bv.y), z2);
    __half2 s2 = __hmax2(__hadd2(*(__half2*)&av.z, *(__half2*)&bv.z), z2);
    __half2 s3 = __hmax2(__hadd2(*(__half2*)&av.w, *(__half2*)&bv.w), z2);

    float2 f0 = __half22float2(s0);
    float2 f1 = __half22float2(s1);
    float2 f2 = __half22float2(s2);
    float2 f3 = __half22float2(s3);

    float p = f0.x * w0.x + f0.y * w0.y
            + f1.x * w0.z + f1.y * w0.w
            + f2.x * w1.x + f2.y * w1.y
            + f3.x * w1.z + f3.y * w1.w;

    // reduce across the 8 lanes of this edge group
    p += __shfl_xor_sync(0xffffffffu, p, 4);
    p += __shfl_xor_sync(0xffffffffu, p, 2);
    p += __shfl_xor_sync(0xffffffffu, p, 1);

    if (t == 0 && e < E) out[e] = p + b2v;
}

// ---------------------------------------------------------------------------
extern "C" void kernel_launch(void* const* d_in, const int* in_sizes, int n_in,
                              void* d_out, int out_size)
{
    const float* emb = (const float*)d_in[0];
    const int*   ei  = (const int*)d_in[1];     // int32 (JAX x64 disabled)
    const float* W1  = (const float*)d_in[2];
    const float* b1  = (const float*)d_in[3];
    const float* W2  = (const float*)d_in[4];
    const float* b2  = (const float*)d_in[5];
    float*       out = (float*)d_out;

    int n_nodes = in_sizes[0] / D;        // 50000
    int E       = in_sizes[1] / 2;        // 800000

    int pre_blocks = (n_nodes + 127) / 128;
    precompute_mma<<<pre_blocks, 256>>>(emb, W1, b1, n_nodes);

    long long warps = ((long long)E + 3) / 4;
    long long threads = warps * 32;
    int blocks = (int)((threads + 255) / 256);
    edge_kernel<<<blocks, 256>>>(ei, W2, b2, out, E);
}

// round 6
// speedup vs baseline: 1.8814x; 1.1203x over previous
#include <cuda_runtime.h>
#include <cuda_fp16.h>

// N=50000 nodes, D=64, E=800000 edges, HID=64.
//   Pa[n][j] = emb[n] . W1[0:64 , j] + b1[j]   (stored fp16)
//   Pb[n][j] = emb[n] . W1[64:128, j]          (stored fp16)
//   out[e]   = W2 . relu(Pa[src[e]] + Pb[dst[e]]) + b2
// R6: edge kernel widened to 8 edges/warp (2 per 8-lane group) -> 4 outstanding
//     gathers, amortized index/W2/store overhead (R5 showed latency x occupancy
//     bound: issue=41%, L2=25%, only 2 gathers in flight).

#define MAX_NODES 50048
#define D 64
#define HID 64

__device__ __half g_Pa[MAX_NODES * HID];   // includes b1
__device__ __half g_Pb[MAX_NODES * HID];

// ---------------------------------------------------------------------------
// Kernel 1: P = emb @ [W1a | W1b]  (50000x64 @ 64x128) via HMMA (unchanged R5).
// ---------------------------------------------------------------------------
__global__ void precompute_mma(const float* __restrict__ emb,
                               const float* __restrict__ W1,
                               const float* __restrict__ b1,
                               int n_nodes)
{
    __shared__ __half As[128 * 72];   // As[r][k]
    __shared__ __half Bs[128 * 72];   // Bs[o][k]

    const int tid = threadIdx.x;
    const int node0 = blockIdx.x * 128;

    {
        int r  = tid >> 1;
        int c0 = (tid & 1) * 32;
        int gn = node0 + r;
        __half2* dst = (__half2*)&As[r * 72 + c0];
        if (gn < n_nodes) {
            const float4* src = (const float4*)(emb + (size_t)gn * D + c0);
            #pragma unroll
            for (int q = 0; q < 8; q++) {
                float4 v = src[q];
                dst[q * 2]     = __floats2half2_rn(v.x, v.y);
                dst[q * 2 + 1] = __floats2half2_rn(v.z, v.w);
            }
        } else {
            #pragma unroll
            for (int q = 0; q < 16; q++) dst[q] = __half2half2(__float2half(0.f));
        }
    }
    for (int i = tid; i < 128 * 64; i += 256) {
        int k = i >> 7, o = i & 127;
        float w = W1[((o < 64) ? k : 64 + k) * HID + (o & 63)];
        Bs[o * 72 + k] = __float2half(w);
    }
    __syncthreads();

    const int warp = tid >> 5, lane = tid & 31;
    const int g = lane >> 2, tig = lane & 3;
    const int mrow = warp * 16;

    float acc[16][4];
    #pragma unroll
    for (int nt = 0; nt < 16; nt++)
        #pragma unroll
        for (int q = 0; q < 4; q++) acc[nt][q] = 0.f;

    #pragma unroll
    for (int kt = 0; kt < 4; kt++) {
        const __half* abase = &As[(mrow + g) * 72 + kt * 16 + tig * 2];
        unsigned int a0 = *(const unsigned int*)(abase);
        unsigned int a1 = *(const unsigned int*)(abase + 8 * 72);
        unsigned int a2 = *(const unsigned int*)(abase + 8);
        unsigned int a3 = *(const unsigned int*)(abase + 8 * 72 + 8);
        #pragma unroll
        for (int nt = 0; nt < 16; nt++) {
            const __half* bbase = &Bs[(nt * 8 + g) * 72 + kt * 16 + tig * 2];
            unsigned int b0 = *(const unsigned int*)(bbase);
            unsigned int b1r = *(const unsigned int*)(bbase + 8);
            asm volatile(
                "mma.sync.aligned.m16n8k16.row.col.f32.f16.f16.f32 "
                "{%0,%1,%2,%3}, {%4,%5,%6,%7}, {%8,%9}, {%0,%1,%2,%3};"
                : "+f"(acc[nt][0]), "+f"(acc[nt][1]), "+f"(acc[nt][2]), "+f"(acc[nt][3])
                : "r"(a0), "r"(a1), "r"(a2), "r"(a3), "r"(b0), "r"(b1r));
        }
    }

    const int nc = tig * 2;
    const int n0 = node0 + mrow + g;
    const int n1 = n0 + 8;
    #pragma unroll
    for (int nt = 0; nt < 16; nt++) {
        int o = nt * 8 + nc;
        float bx = 0.f, by = 0.f;
        if (o < 64) { bx = b1[o]; by = b1[o + 1]; }
        __half* tab = (o < 64) ? g_Pa : g_Pb;
        int col = o & 63;
        if (n0 < n_nodes)
            *(__half2*)(tab + (size_t)n0 * HID + col) =
                __floats2half2_rn(acc[nt][0] + bx, acc[nt][1] + by);
        if (n1 < n_nodes)
            *(__half2*)(tab + (size_t)n1 * HID + col) =
                __floats2half2_rn(acc[nt][2] + bx, acc[nt][3] + by);
    }
}

// ---------------------------------------------------------------------------
// Kernel 2: gather + relu + dot(W2). 8 lanes/edge-group, 2 edges per group,
// 8 edges/warp. 4 gather LDG.128 in flight per group; float2 output store.
// ---------------------------------------------------------------------------
__device__ __forceinline__ float edge_dot(uint4 av, uint4 bv,
                                          float4 w0, float4 w1)
{
    const __half2 z2 = __half2half2(__float2half(0.f));
    __half2 s0 = __hmax2(__hadd2(*(__half2*)&av.x, *(__half2*)&bv.x), z2);
    __half2 s1 = __hmax2(__hadd2(*(__half2*)&av.y, *(__half2*)&bv.y), z2);
    __half2 s2 = __hmax2(__hadd2(*(__half2*)&av.z, *(__half2*)&bv.z), z2);
    __half2 s3 = __hmax2(__hadd2(*(__half2*)&av.w, *(__half2*)&bv.w), z2);
    float2 f0 = __half22float2(s0);
    float2 f1 = __half22float2(s1);
    float2 f2 = __half22float2(s2);
    float2 f3 = __half22float2(s3);
    return f0.x * w0.x + f0.y * w0.y
         + f1.x * w0.z + f1.y * w0.w
         + f2.x * w1.x + f2.y * w1.y
         + f3.x * w1.z + f3.y * w1.w;
}

__global__ void edge_kernel(const int* __restrict__ ei,
                            const float* __restrict__ W2,
                            const float* __restrict__ b2,
                            float* __restrict__ out,
                            int E)
{
    int gtid = blockIdx.x * blockDim.x + threadIdx.x;
    int warp = gtid >> 5;
    int lane = threadIdx.x & 31;
    int t = lane & 7;                // slot within edge group
    int g = lane >> 3;               // edge group 0..3

    float4 w0 = *(const float4*)(W2 + (t << 3));
    float4 w1 = *(const float4*)(W2 + (t << 3) + 4);
    float b2v = __ldg(b2);

    int e0 = (warp * 4 + g) * 2;     // first of 2 consecutive edges
    int ec = e0;
    if (ec + 2 > E) ec = E - 2;      // clamp pair base (E >= 2)
    if (ec < 0) ec = 0;

    long long sp = 0, dp = 0;
    if (t == 0) {
        sp = *(const long long*)(ei + ec);        // src[ec], src[ec+1]
        dp = *(const long long*)(ei + E + ec);    // dst[ec], dst[ec+1]
    }
    sp = __shfl_sync(0xffffffffu, sp, lane & 24);
    dp = __shfl_sync(0xffffffffu, dp, lane & 24);
    int s0 = (int)(unsigned int)(sp & 0xffffffffLL);
    int s1 = (int)(unsigned int)((unsigned long long)sp >> 32);
    int d0 = (int)(unsigned int)(dp & 0xffffffffLL);
    int d1 = (int)(unsigned int)((unsigned long long)dp >> 32);

    // 4 independent 128B gathers in flight
    uint4 A0 = ((const uint4*)(g_Pa + (size_t)s0 * HID))[t];
    uint4 B0 = ((const uint4*)(g_Pb + (size_t)d0 * HID))[t];
    uint4 A1 = ((const uint4*)(g_Pa + (size_t)s1 * HID))[t];
    uint4 B1 = ((const uint4*)(g_Pb + (size_t)d1 * HID))[t];

    float p0 = edge_dot(A0, B0, w0, w1);
    float p1 = edge_dot(A1, B1, w0, w1);

    #pragma unroll
    for (int m = 4; m >= 1; m >>= 1) {
        p0 += __shfl_xor_sync(0xffffffffu, p0, m);
        p1 += __shfl_xor_sync(0xffffffffu, p1, m);
    }

    if (t == 0) {
        if (e0 == ec) {
            // normal path: store both edges as one float2 (8B aligned, e0 even)
            float2 r; r.x = p0 + b2v; r.y = p1 + b2v;
            *(float2*)(out + e0) = r;
        } else if (e0 < E) {
            // odd tail: ec = E-2, this group's real edge is e0 = E-1 = ec+1
            out[e0] = p1 + b2v;
        }
    }
}

// ---------------------------------------------------------------------------
extern "C" void kernel_launch(void* const* d_in, const int* in_sizes, int n_in,
                              void* d_out, int out_size)
{
    const float* emb = (const float*)d_in[0];
    const int*   ei  = (const int*)d_in[1];     // int32 (JAX x64 disabled)
    const float* W1  = (const float*)d_in[2];
    const float* b1  = (const float*)d_in[3];
    const float* W2  = (const float*)d_in[4];
    const float* b2  = (const float*)d_in[5];
    float*       out = (float*)d_out;

    int n_nodes = in_sizes[0] / D;        // 50000
    int E       = in_sizes[1] / 2;        // 800000

    int pre_blocks = (n_nodes + 127) / 128;
    precompute_mma<<<pre_blocks, 256>>>(emb, W1, b1, n_nodes);

    long long warps = ((long long)E + 7) / 8;
    long long threads = warps * 32;
    int blocks = (int)((threads + 255) / 256);
    edge_kernel<<<blocks, 256>>>(ei, W2, b2, out, E);
}

// round 7
// speedup vs baseline: 2.0641x; 1.0971x over previous
#include <cuda_runtime.h>
#include <cuda_fp16.h>

// N=50000 nodes, D=64, E=800000 edges, HID=64.
//   Pa[n][j] = emb[n] . W1[0:64 , j] + b1[j]   (stored fp16)
//   Pb[n][j] = emb[n] . W1[64:128, j]          (stored fp16)
//   out[e]   = W2 . relu(Pa[src[e]] + Pb[dst[e]]) + b2
// R7: 16 edges/warp (4 per 8-lane group), 8 gathers in flight, broadcast int4
//     index loads (no shfl on the index path), float4 output stores.

#define MAX_NODES 50048
#define D 64
#define HID 64

__device__ __half g_Pa[MAX_NODES * HID];   // includes b1
__device__ __half g_Pb[MAX_NODES * HID];

// ---------------------------------------------------------------------------
// Kernel 1: P = emb @ [W1a | W1b]  (50000x64 @ 64x128) via HMMA (unchanged).
// ---------------------------------------------------------------------------
__global__ void precompute_mma(const float* __restrict__ emb,
                               const float* __restrict__ W1,
                               const float* __restrict__ b1,
                               int n_nodes)
{
    __shared__ __half As[128 * 72];   // As[r][k]
    __shared__ __half Bs[128 * 72];   // Bs[o][k]

    const int tid = threadIdx.x;
    const int node0 = blockIdx.x * 128;

    {
        int r  = tid >> 1;
        int c0 = (tid & 1) * 32;
        int gn = node0 + r;
        __half2* dst = (__half2*)&As[r * 72 + c0];
        if (gn < n_nodes) {
            const float4* src = (const float4*)(emb + (size_t)gn * D + c0);
            #pragma unroll
            for (int q = 0; q < 8; q++) {
                float4 v = src[q];
                dst[q * 2]     = __floats2half2_rn(v.x, v.y);
                dst[q * 2 + 1] = __floats2half2_rn(v.z, v.w);
            }
        } else {
            #pragma unroll
            for (int q = 0; q < 16; q++) dst[q] = __half2half2(__float2half(0.f));
        }
    }
    for (int i = tid; i < 128 * 64; i += 256) {
        int k = i >> 7, o = i & 127;
        float w = W1[((o < 64) ? k : 64 + k) * HID + (o & 63)];
        Bs[o * 72 + k] = __float2half(w);
    }
    __syncthreads();

    const int warp = tid >> 5, lane = tid & 31;
    const int g = lane >> 2, tig = lane & 3;
    const int mrow = warp * 16;

    float acc[16][4];
    #pragma unroll
    for (int nt = 0; nt < 16; nt++)
        #pragma unroll
        for (int q = 0; q < 4; q++) acc[nt][q] = 0.f;

    #pragma unroll
    for (int kt = 0; kt < 4; kt++) {
        const __half* abase = &As[(mrow + g) * 72 + kt * 16 + tig * 2];
        unsigned int a0 = *(const unsigned int*)(abase);
        unsigned int a1 = *(const unsigned int*)(abase + 8 * 72);
        unsigned int a2 = *(const unsigned int*)(abase + 8);
        unsigned int a3 = *(const unsigned int*)(abase + 8 * 72 + 8);
        #pragma unroll
        for (int nt = 0; nt < 16; nt++) {
            const __half* bbase = &Bs[(nt * 8 + g) * 72 + kt * 16 + tig * 2];
            unsigned int b0 = *(const unsigned int*)(bbase);
            unsigned int b1r = *(const unsigned int*)(bbase + 8);
            asm volatile(
                "mma.sync.aligned.m16n8k16.row.col.f32.f16.f16.f32 "
                "{%0,%1,%2,%3}, {%4,%5,%6,%7}, {%8,%9}, {%0,%1,%2,%3};"
                : "+f"(acc[nt][0]), "+f"(acc[nt][1]), "+f"(acc[nt][2]), "+f"(acc[nt][3])
                : "r"(a0), "r"(a1), "r"(a2), "r"(a3), "r"(b0), "r"(b1r));
        }
    }

    const int nc = tig * 2;
    const int n0 = node0 + mrow + g;
    const int n1 = n0 + 8;
    #pragma unroll
    for (int nt = 0; nt < 16; nt++) {
        int o = nt * 8 + nc;
        float bx = 0.f, by = 0.f;
        if (o < 64) { bx = b1[o]; by = b1[o + 1]; }
        __half* tab = (o < 64) ? g_Pa : g_Pb;
        int col = o & 63;
        if (n0 < n_nodes)
            *(__half2*)(tab + (size_t)n0 * HID + col) =
                __floats2half2_rn(acc[nt][0] + bx, acc[nt][1] + by);
        if (n1 < n_nodes)
            *(__half2*)(tab + (size_t)n1 * HID + col) =
                __floats2half2_rn(acc[nt][2] + bx, acc[nt][3] + by);
    }
}

// ---------------------------------------------------------------------------
// Kernel 2: gather + relu + dot(W2). 8 lanes/group, 4 edges/group, 16/warp.
// ---------------------------------------------------------------------------
__device__ __forceinline__ float edge_dot(uint4 av, uint4 bv,
                                          float4 w0, float4 w1)
{
    const __half2 z2 = __half2half2(__float2half(0.f));
    __half2 s0 = __hmax2(__hadd2(*(__half2*)&av.x, *(__half2*)&bv.x), z2);
    __half2 s1 = __hmax2(__hadd2(*(__half2*)&av.y, *(__half2*)&bv.y), z2);
    __half2 s2 = __hmax2(__hadd2(*(__half2*)&av.z, *(__half2*)&bv.z), z2);
    __half2 s3 = __hmax2(__hadd2(*(__half2*)&av.w, *(__half2*)&bv.w), z2);
    float2 f0 = __half22float2(s0);
    float2 f1 = __half22float2(s1);
    float2 f2 = __half22float2(s2);
    float2 f3 = __half22float2(s3);
    return f0.x * w0.x + f0.y * w0.y
         + f1.x * w0.z + f1.y * w0.w
         + f2.x * w1.x + f2.y * w1.y
         + f3.x * w1.z + f3.y * w1.w;
}

__global__ void __launch_bounds__(256)
edge_kernel(const int* __restrict__ ei,
            const float* __restrict__ W2,
            const float* __restrict__ b2,
            float* __restrict__ out,
            int E)
{
    int gtid = blockIdx.x * blockDim.x + threadIdx.x;
    int warp = gtid >> 5;
    int lane = threadIdx.x & 31;
    int t = lane & 7;                // slot within edge group
    int g = lane >> 3;               // edge group 0..3

    float4 w0 = *(const float4*)(W2 + (t << 3));
    float4 w1 = *(const float4*)(W2 + (t << 3) + 4);
    float b2v = __ldg(b2);

    int e0 = warp * 16 + g * 4;      // first of 4 consecutive edges
    int ec = e0;
    if (ec + 4 > E) ec = (E >= 4) ? (E - 4) : 0;   // clamp (overlap recompute ok)

    // Index loads: every lane of the group reads the same int4 -> 1 line, bcast.
    int4 sv, dv;
    if (((E | ec) & 3) == 0) {
        sv = *(const int4*)(ei + ec);
        dv = *(const int4*)(ei + E + ec);
    } else {
        sv.x = ei[ec];     sv.y = ei[ec + 1];     sv.z = ei[ec + 2];     sv.w = ei[ec + 3];
        dv.x = ei[E + ec]; dv.y = ei[E + ec + 1]; dv.z = ei[E + ec + 2]; dv.w = ei[E + ec + 3];
    }

    // 8 independent 128B gathers in flight
    uint4 A0 = ((const uint4*)(g_Pa + (size_t)sv.x * HID))[t];
    uint4 B0 = ((const uint4*)(g_Pb + (size_t)dv.x * HID))[t];
    uint4 A1 = ((const uint4*)(g_Pa + (size_t)sv.y * HID))[t];
    uint4 B1 = ((const uint4*)(g_Pb + (size_t)dv.y * HID))[t];
    uint4 A2 = ((const uint4*)(g_Pa + (size_t)sv.z * HID))[t];
    uint4 B2 = ((const uint4*)(g_Pb + (size_t)dv.z * HID))[t];
    uint4 A3 = ((const uint4*)(g_Pa + (size_t)sv.w * HID))[t];
    uint4 B3 = ((const uint4*)(g_Pb + (size_t)dv.w * HID))[t];

    float p0 = edge_dot(A0, B0, w0, w1);
    float p1 = edge_dot(A1, B1, w0, w1);
    float p2 = edge_dot(A2, B2, w0, w1);
    float p3 = edge_dot(A3, B3, w0, w1);

    #pragma unroll
    for (int m = 4; m >= 1; m >>= 1) {
        p0 += __shfl_xor_sync(0xffffffffu, p0, m);
        p1 += __shfl_xor_sync(0xffffffffu, p1, m);
        p2 += __shfl_xor_sync(0xffffffffu, p2, m);
        p3 += __shfl_xor_sync(0xffffffffu, p3, m);
    }

    if (t == 0 && ec < E) {
        if ((ec & 3) == 0 && ec + 4 <= E) {
            float4 r;
            r.x = p0 + b2v; r.y = p1 + b2v; r.z = p2 + b2v; r.w = p3 + b2v;
            *(float4*)(out + ec) = r;        // duplicates on clamp are identical
        } else {
            if (ec < E)     out[ec]     = p0 + b2v;
            if (ec + 1 < E) out[ec + 1] = p1 + b2v;
            if (ec + 2 < E) out[ec + 2] = p2 + b2v;
            if (ec + 3 < E) out[ec + 3] = p3 + b2v;
        }
    }
}

// ---------------------------------------------------------------------------
extern "C" void kernel_launch(void* const* d_in, const int* in_sizes, int n_in,
                              void* d_out, int out_size)
{
    const float* emb = (const float*)d_in[0];
    const int*   ei  = (const int*)d_in[1];     // int32 (JAX x64 disabled)
    const float* W1  = (const float*)d_in[2];
    const float* b1  = (const float*)d_in[3];
    const float* W2  = (const float*)d_in[4];
    const float* b2  = (const float*)d_in[5];
    float*       out = (float*)d_out;

    int n_nodes = in_sizes[0] / D;        // 50000
    int E       = in_sizes[1] / 2;        // 800000

    int pre_blocks = (n_nodes + 127) / 128;
    precompute_mma<<<pre_blocks, 256>>>(emb, W1, b1, n_nodes);

    long long warps = ((long long)E + 15) / 16;
    long long threads = warps * 32;
    int blocks = (int)((threads + 255) / 256);
    edge_kernel<<<blocks, 256>>>(ei, W2, b2, out, E);
}